// round 15
// baseline (speedup 1.0000x reference)
#include <cuda_runtime.h>
#include <cstdint>
#include <math.h>

// Problem constants
#define BNN   2048
#define FF    768
#define EE    65536
#define BB    8
#define LLQ   64
#define NREL  3
#define NBINS (BNN*NREL)
#define K4    3072
#define K2    1536

// ------------------------- device scratch -------------------------
__device__ int   g_bin_cnt[NBINS];
__device__ int   g_bin_off[NBINS];
__device__ int   g_cursor[NBINS];
__device__ float g_inv_cnt[NBINS];
__device__ int   g_sorted_src[EE];
__device__ float g_X4[(size_t)BNN * K4];
__device__ float g_WcatT[2][(size_t)FF * K4];
__device__ float g_H[(size_t)BNN * K2];
__device__ float g_Wgr[(size_t)FF * 2 * FF];
__device__ float g_Wqr[(size_t)FF * 2 * FF];
__device__ float g_WB[(size_t)K2 * FF];       // [Wg_h ; Wq_h]  (1536 x 768)
__device__ float g_qr[(size_t)BB * LLQ * FF];
__device__ float g_P[(size_t)BNN * 5376];     // 2 slices M x 1536 + 3 slices M x 768
__device__ float g_QGp[(size_t)3 * BB * LLQ * FF];

__device__ __forceinline__ float sigmoidf_(float x) {
    return __fdividef(1.0f, 1.0f + __expf(-x));
}
__device__ __forceinline__ float tanh_fast(float x) {
    float e = __expf(2.0f * x);
    return 1.0f - __fdividef(2.0f, e + 1.0f);
}
__device__ __forceinline__ float to_tf32(float x) {
    uint32_t u;
    asm("cvt.rna.tf32.f32 %0, %1;" : "=r"(u) : "f"(x));
    return __uint_as_float(u);
}
__device__ __forceinline__ float4 r4(float4 v) {
    return make_float4(to_tf32(v.x), to_tf32(v.y), to_tf32(v.z), to_tf32(v.w));
}
__device__ __forceinline__ float rcp_fast(float x) {
    float r;
    asm("rcp.approx.ftz.f32 %0, %1;" : "=f"(r) : "f"(x));
    return r;
}
__device__ __forceinline__ uint32_t smem_u32(const void* p) {
    uint32_t a;
    asm("{ .reg .u64 t; cvta.to.shared.u64 t, %1; cvt.u32.u64 %0, t; }" : "=r"(a) : "l"(p));
    return a;
}
__device__ __forceinline__ void cp16(uint32_t dst, const void* src) {
    asm volatile("cp.async.cg.shared.global [%0], [%1], 16;" :: "r"(dst), "l"(src));
}
#define CP_COMMIT() asm volatile("cp.async.commit_group;" ::: "memory")
#define CP_WAIT1()  asm volatile("cp.async.wait_group 1;" ::: "memory")
#define CP_WAIT0()  asm volatile("cp.async.wait_group 0;" ::: "memory")

#define MMA_TF32(D, Aa, b0v, b1v) \
    asm volatile("mma.sync.aligned.m16n8k8.row.col.f32.tf32.tf32.f32 " \
        "{%0,%1,%2,%3}, {%4,%5,%6,%7}, {%8,%9}, {%0,%1,%2,%3};" \
        : "+f"((D)[0]), "+f"((D)[1]), "+f"((D)[2]), "+f"((D)[3]) \
        : "r"((Aa)[0]), "r"((Aa)[1]), "r"((Aa)[2]), "r"((Aa)[3]), \
          "r"(b0v), "r"(b1v))

__device__ __forceinline__ void ldsm4(uint32_t addr, uint32_t* r) {
    asm volatile("ldmatrix.sync.aligned.m8n8.x4.shared.b16 {%0,%1,%2,%3}, [%4];"
        : "=r"(r[0]), "=r"(r[1]), "=r"(r[2]), "=r"(r[3]) : "r"(addr));
}

// ------------------------- CSR build -------------------------
__global__ void k_hist(const int* __restrict__ ei, const int* __restrict__ et) {
    int i = blockIdx.x * blockDim.x + threadIdx.x;
    if (i < EE) {
        int dst = ei[EE + i];
        atomicAdd(&g_bin_cnt[dst * NREL + et[i]], 1);
    }
}

__global__ void k_scan() {
    __shared__ int wsum[32];
    int t = threadIdx.x;
    int c[6], loc[6];
    int s = 0;
#pragma unroll
    for (int j = 0; j < 6; ++j) { c[j] = g_bin_cnt[t * 6 + j]; loc[j] = s; s += c[j]; }
    int lane = t & 31, w = t >> 5;
    int v = s;
#pragma unroll
    for (int d = 1; d < 32; d <<= 1) { int u = __shfl_up_sync(0xffffffffu, v, d); if (lane >= d) v += u; }
    if (lane == 31) wsum[w] = v;
    __syncthreads();
    if (w == 0) {
        int u = wsum[lane];
#pragma unroll
        for (int d = 1; d < 32; d <<= 1) { int z = __shfl_up_sync(0xffffffffu, u, d); if (lane >= d) u += z; }
        wsum[lane] = u;
    }
    __syncthreads();
    int base = (w > 0 ? wsum[w - 1] : 0) + (v - s);
#pragma unroll
    for (int j = 0; j < 6; ++j) {
        int idx = t * 6 + j;
        int off = base + loc[j];
        g_bin_off[idx] = off;
        g_cursor[idx]  = off;
        g_inv_cnt[idx] = 1.0f / (float)(c[j] > 0 ? c[j] : 1);
    }
}

__global__ void k_fill(const int* __restrict__ ei, const int* __restrict__ et) {
    int i = blockIdx.x * blockDim.x + threadIdx.x;
    if (i < EE) {
        int dst = ei[EE + i];
        int pos = atomicAdd(&g_cursor[dst * NREL + et[i]], 1);
        g_sorted_src[pos] = ei[i];
    }
}

// ------------------------- fused prep -------------------------
#define N_WG4 (FF * 2 * FF / 4)
#define N_Q4  (BB * LLQ * FF / 4)
#define N_X4  (BNN * FF / 4)
#define N_PREP (2 * N_WG4 + N_Q4 + N_X4)

__global__ void k_prep(const float4* __restrict__ Wg, const float4* __restrict__ Wq,
                       const float4* __restrict__ q, const float4* __restrict__ x) {
    int i = blockIdx.x * blockDim.x + threadIdx.x;
    if (i < NBINS) g_bin_cnt[i] = 0;
    if (i >= N_PREP) return;
    if (i < N_WG4) {
        float4 v = r4(Wg[i]);
        reinterpret_cast<float4*>(g_Wgr)[i] = v;
        int n = i / 384, c4 = i - n * 384;
        if (c4 < 192) reinterpret_cast<float4*>(g_WB)[n * 192 + c4] = v;        // Wg_h -> WB rows 0..767
    } else if (i < 2 * N_WG4) {
        int j = i - N_WG4;
        float4 v = r4(Wq[j]);
        reinterpret_cast<float4*>(g_Wqr)[j] = v;
        int n = j / 384, c4 = j - n * 384;
        if (c4 < 192) reinterpret_cast<float4*>(g_WB)[(FF + n) * 192 + c4] = v;  // Wq_h -> WB rows 768..1535
    } else if (i < 2 * N_WG4 + N_Q4) {
        int j = i - 2 * N_WG4;
        reinterpret_cast<float4*>(g_qr)[j] = r4(q[j]);
    } else {
        int j = i - 2 * N_WG4 - N_Q4;
        int row = j / 192, c = j - row * 192;
        reinterpret_cast<float4*>(g_X4)[(size_t)row * 768 + c] = r4(x[j]);
    }
}

// Dual-layer transpose
__global__ void __launch_bounds__(256) k_transpose_w2(
    const float* __restrict__ Wroot1, const float* __restrict__ Wrel1,
    const float* __restrict__ Wroot2, const float* __restrict__ Wrel2) {
    __shared__ float t[32][33];
    int kb = blockIdx.x * 32, nb = blockIdx.y * 32;
    int layer = blockIdx.z;
    const float* Wroot = layer ? Wroot2 : Wroot1;
    const float* Wrel  = layer ? Wrel2  : Wrel1;
    int tx = threadIdx.x, ty = threadIdx.y;
#pragma unroll
    for (int j = 0; j < 4; ++j) {
        int k = kb + ty + j * 8;
        float v = (k < FF) ? Wroot[(size_t)k * FF + nb + tx]
                           : Wrel[(size_t)(k - FF) * FF + nb + tx];
        t[ty + j * 8][tx] = to_tf32(v);
    }
    __syncthreads();
#pragma unroll
    for (int j = 0; j < 4; ++j) {
        int n = nb + ty + j * 8;
        g_WcatT[layer][(size_t)n * K4 + kb + tx] = t[tx][ty + j * 8];
    }
}

// ------------------------- aggregation -------------------------
__global__ void __launch_bounds__(192) k_aggregate() {
    int bin = blockIdx.x;
    int dst = bin / NREL;
    int rel = bin - dst * NREL;
    int beg = g_bin_off[bin];
    int cnt = g_bin_cnt[bin];
    int t = threadIdx.x;
    const float4* x4 = reinterpret_cast<const float4*>(g_X4);
    float4 acc = make_float4(0.f, 0.f, 0.f, 0.f);
    int sNext = (cnt > 0) ? g_sorted_src[beg] : 0;
    for (int j = 0; j < cnt; ++j) {
        int s = sNext;
        if (j + 1 < cnt) sNext = g_sorted_src[beg + j + 1];
        float4 v = x4[(size_t)s * 768 + t];
        acc.x += v.x; acc.y += v.y; acc.z += v.z; acc.w += v.w;
    }
    float ic = g_inv_cnt[bin];
    acc.x *= ic; acc.y *= ic; acc.z *= ic; acc.w *= ic;
    reinterpret_cast<float4*>(g_X4)[(size_t)dst * 768 + (size_t)(rel + 1) * 192 + t] = r4(acc);
}

// ------------------------- split-K tf32 mma.sync GEMM (R12 core, ldp param) ------
// P[z][M][ldp] partial = A[M, kOff:kOff+Kh] @ B[:, kOff:kOff+Kh]^T  (CTA n0 window)
// CTA tile 128x128, 128 threads = 4 warps (2m x 2n) of 64x64 warp tiles.
#define MT 128
#define NT 128
#define STAGE_FLOATS ((MT + NT) * 32)
#define STAGE_BYTES  (STAGE_FLOATS * 4)
#define SMEM_MMA_BYTES (3 * STAGE_BYTES)

__global__ void __launch_bounds__(128, 2) k_mma_sk(
    const float* __restrict__ A, int lda,
    const float* __restrict__ B, int ldb,
    float* __restrict__ P, int ldp, int Kh)
{
    extern __shared__ float sm[];
    const int tid = threadIdx.x;
    const int m0 = blockIdx.y * MT;
    const int n0 = blockIdx.x * NT;
    const int Mtot = gridDim.y * MT;
    const int kOff = blockIdx.z * Kh;
    const int wid = tid >> 5, lane = tid & 31;
    const int wm = (wid >> 1) * 64;
    const int wn = (wid & 1) * 64;
    const int g = lane >> 2, t = lane & 3;

    const uint32_t smb = smem_u32(sm);

    const int crow = tid >> 3;
    const int cc = tid & 7;
    const uint32_t physc = (uint32_t)(cc ^ (crow & 7)) * 16u;

    const int l7 = lane & 7, l8 = (lane >> 3) & 1, l16 = (lane >> 4) & 1;
    uint32_t aRow[4];
#pragma unroll
    for (int mt = 0; mt < 4; ++mt)
        aRow[mt] = (uint32_t)(wm + mt * 16 + l7 + l8 * 8) * 128u;
    uint32_t bRow[4];
#pragma unroll
    for (int p = 0; p < 4; ++p)
        bRow[p] = (uint32_t)(MT * 32 * 4) + (uint32_t)(wn + p * 16 + l7 + l16 * 8) * 128u;

    float d[4][8][4];
#pragma unroll
    for (int mt = 0; mt < 4; ++mt)
#pragma unroll
        for (int nt = 0; nt < 8; ++nt)
#pragma unroll
            for (int j = 0; j < 4; ++j) d[mt][nt][j] = 0.f;

    const int nk = Kh >> 5;
    const float* Abase = A + (size_t)(m0 + crow) * lda + kOff + cc * 4;
    const float* Bbase = B + (size_t)(n0 + crow) * ldb + kOff + cc * 4;

    auto issue = [&](int c, int s) {
        uint32_t st = smb + (uint32_t)s * STAGE_BYTES;
        int k0 = c << 5;
#pragma unroll
        for (int i = 0; i < 8; ++i)
            cp16(st + (uint32_t)(crow + 16 * i) * 128u + physc,
                 Abase + (size_t)(16 * i) * lda + k0);
#pragma unroll
        for (int i = 0; i < 8; ++i)
            cp16(st + (uint32_t)(MT * 32 * 4) + (uint32_t)(crow + 16 * i) * 128u + physc,
                 Bbase + (size_t)(16 * i) * ldb + k0);
        CP_COMMIT();
    };

    issue(0, 0);
    if (nk > 1) issue(1, 1);

    int sIss = 2, sCur = 0;
    for (int c = 0; c < nk; ++c) {
        if (c + 1 < nk) CP_WAIT1(); else CP_WAIT0();
        __syncthreads();
        if (c + 2 < nk) { issue(c + 2, sIss); sIss = (sIss == 2) ? 0 : sIss + 1; }

        uint32_t st = smb + (uint32_t)sCur * STAGE_BYTES;
        sCur = (sCur == 2) ? 0 : sCur + 1;

#pragma unroll
        for (int ks = 0; ks < 4; ++ks) {
            uint32_t kaOff = (uint32_t)(((ks * 2 + l16) ^ l7) * 16);
            uint32_t kbOff = (uint32_t)(((ks * 2 + l8) ^ l7) * 16);
            uint32_t aF[4][4], bF[4][4];
#pragma unroll
            for (int mt = 0; mt < 4; ++mt) ldsm4(st + aRow[mt] + kaOff, aF[mt]);
#pragma unroll
            for (int p = 0; p < 4; ++p)    ldsm4(st + bRow[p] + kbOff, bF[p]);
#pragma unroll
            for (int mt = 0; mt < 4; ++mt)
#pragma unroll
                for (int p = 0; p < 4; ++p) {
                    MMA_TF32(d[mt][2 * p],     aF[mt], bF[p][0], bF[p][1]);
                    MMA_TF32(d[mt][2 * p + 1], aF[mt], bF[p][2], bF[p][3]);
                }
        }
    }

    float* Cp = P + (size_t)blockIdx.z * Mtot * ldp;
#pragma unroll
    for (int mt = 0; mt < 4; ++mt)
#pragma unroll
        for (int nt = 0; nt < 8; ++nt) {
            int ccc = n0 + wn + nt * 8 + t * 2;
#pragma unroll
            for (int h = 0; h < 2; ++h) {
                int r = m0 + wm + mt * 16 + g + h * 8;
                float2 v = make_float2(d[mt][nt][h * 2 + 0], d[mt][nt][h * 2 + 1]);
                *reinterpret_cast<float2*>(Cp + (size_t)r * ldp + ccc) = v;
            }
        }
}

// ------------------------- RGCN combine (3 slices, ld 768) + relu ----------------
__global__ void k_combine_relu(const float* __restrict__ P, float* __restrict__ C,
                               const float* __restrict__ bias) {
    int i = blockIdx.x * blockDim.x + threadIdx.x;
    if (i >= BNN * 192) return;
    int row = i / 192, c4 = i - row * 192;
    const float4* P4 = reinterpret_cast<const float4*>(P);
    float4 v = P4[(size_t)row * 192 + c4];
#pragma unroll
    for (int z = 1; z < 3; ++z) {
        float4 b = P4[(size_t)(z * BNN + row) * 192 + c4];
        v.x += b.x; v.y += b.y; v.z += b.z; v.w += b.w;
    }
    float4 b4 = reinterpret_cast<const float4*>(bias)[c4];
    v.x = to_tf32(fmaxf(v.x + b4.x, 0.f)); v.y = to_tf32(fmaxf(v.y + b4.y, 0.f));
    v.z = to_tf32(fmaxf(v.z + b4.z, 0.f)); v.w = to_tf32(fmaxf(v.w + b4.w, 0.f));
    *reinterpret_cast<float4*>(C + (size_t)row * K2 + c4 * 4) = v;
}

// ------------------------- gate combine: alpha from Pg cols 768.. + Paqi ---------
// ROUND=1: tf32-round and write to C (ld K4, X4); ROUND=0: raw write (ld FF, out)
template<int ROUND>
__global__ void k_gcombine(const float* __restrict__ Pg, const float* __restrict__ Paqi,
                           float* __restrict__ C, int ldc,
                           const float* __restrict__ bias, const float* __restrict__ Hbuf) {
    int i = blockIdx.x * blockDim.x + threadIdx.x;
    if (i >= BNN * 192) return;
    int row = i / 192, c4 = i - row * 192;
    int col = c4 * 4;
    const float4* Pg4 = reinterpret_cast<const float4*>(Pg);
    const float4* Pa4 = reinterpret_cast<const float4*>(Paqi);
    // alpha_h: Pg rows have 1536 floats (384 float4); cols 768.. start at +192
    float4 v = Pg4[(size_t)row * 384 + 192 + c4];
    {
        float4 b = Pg4[(size_t)(BNN + row) * 384 + 192 + c4];
        v.x += b.x; v.y += b.y; v.z += b.z; v.w += b.w;
    }
#pragma unroll
    for (int z = 0; z < 3; ++z) {
        float4 b = Pa4[(size_t)(z * BNN + row) * 192 + c4];
        v.x += b.x; v.y += b.y; v.z += b.z; v.w += b.w;
    }
    float4 b4 = reinterpret_cast<const float4*>(bias)[c4];
    v.x += b4.x; v.y += b4.y; v.z += b4.z; v.w += b4.w;

    const float* hp = Hbuf + (size_t)row * K2 + col;
    float4 h4  = *reinterpret_cast<const float4*>(hp);
    float4 qi4 = *reinterpret_cast<const float4*>(hp + FF);
    float al;
    al = sigmoidf_(v.x); v.x = al * tanh_fast(qi4.x) + (1.f - al) * h4.x;
    al = sigmoidf_(v.y); v.y = al * tanh_fast(qi4.y) + (1.f - al) * h4.y;
    al = sigmoidf_(v.z); v.z = al * tanh_fast(qi4.z) + (1.f - al) * h4.z;
    al = sigmoidf_(v.w); v.w = al * tanh_fast(qi4.w) + (1.f - al) * h4.w;
    if (ROUND) v = r4(v);
    *reinterpret_cast<float4*>(C + (size_t)row * ldc + col) = v;
}

// ------------------------- fused qi (hg from 2 Pg slices, ld 1536) ---------------
__global__ void __launch_bounds__(96) k_qi(const float* __restrict__ q,
                                           const float* __restrict__ bg) {
    int fb = blockIdx.x;
    int nq = blockIdx.y;
    int b  = blockIdx.z;
    int t  = threadIdx.x;
    int f  = fb * 96 + t;

    __shared__ float qs[LLQ * 96];
    float eq[LLQ];
    float bgv = bg[f];
#pragma unroll
    for (int l = 0; l < LLQ; ++l) {
        size_t qidx = ((size_t)(b * LLQ + l)) * FF + f;
        float qgv = bgv;
#pragma unroll
        for (int z = 0; z < 3; ++z) qgv += g_QGp[(size_t)z * BB * LLQ * FF + qidx];
        qgv = fminf(fmaxf(qgv, -60.f), 60.f);
        eq[l] = __expf(-qgv);
        qs[l * 96 + t] = q[qidx];
    }
    __syncthreads();

    int n0 = nq * 32;
    for (int n = n0; n < n0 + 32; n += 2) {
        int node = b * 256 + n;
        size_t hidx = (size_t)node * K2 + f;   // Pg row stride 1536
        float hg0 = g_P[hidx]              + g_P[(size_t)BNN * K2 + hidx];
        float hg1 = g_P[hidx + K2]         + g_P[(size_t)BNN * K2 + hidx + K2];
        hg0 = fminf(fmaxf(hg0, -60.f), 60.f);
        hg1 = fminf(fmaxf(hg1, -60.f), 60.f);
        float eh0 = __expf(-hg0), eh1 = __expf(-hg1);
        float acc0 = 0.f, acc1 = 0.f;
#pragma unroll
        for (int l = 0; l < LLQ; ++l) {
            float qv = qs[l * 96 + t];
            float d0 = fmaf(eh0, eq[l], 1.0f);
            float d1 = fmaf(eh1, eq[l], 1.0f);
            float r = rcp_fast(d0 * d1);
            acc0 = fmaf(r * d1, qv, acc0);
            acc1 = fmaf(r * d0, qv, acc1);
        }
        g_H[(size_t)node * K2 + FF + f]       = to_tf32(acc0);
        g_H[(size_t)(node + 1) * K2 + FF + f] = to_tf32(acc1);
    }
}

// ------------------------- host -------------------------
extern "C" void kernel_launch(void* const* d_in, const int* in_sizes, int n_in,
                              void* d_out, int out_size) {
    const float* x     = (const float*)d_in[0];
    const int*   ei    = (const int*)  d_in[1];
    const int*   et    = (const int*)  d_in[2];
    const float* q     = (const float*)d_in[3];
    const float* Wrel1 = (const float*)d_in[4];
    const float* Wrt1  = (const float*)d_in[5];
    const float* b1    = (const float*)d_in[6];
    const float* Wrel2 = (const float*)d_in[7];
    const float* Wrt2  = (const float*)d_in[8];
    const float* b2    = (const float*)d_in[9];
    const float* Wg    = (const float*)d_in[10];
    const float* bg    = (const float*)d_in[11];
    const float* Wq    = (const float*)d_in[12];
    const float* bq    = (const float*)d_in[13];
    float* out = (float*)d_out;

    float *pX4, *pWT0, *pWT1, *pH, *pWgr, *pWqr, *pWB, *pqr, *pP, *pQGp;
    cudaGetSymbolAddress((void**)&pX4,  g_X4);
    cudaGetSymbolAddress((void**)&pWT0, g_WcatT);
    pWT1 = pWT0 + (size_t)FF * K4;
    cudaGetSymbolAddress((void**)&pH,   g_H);
    cudaGetSymbolAddress((void**)&pWgr, g_Wgr);
    cudaGetSymbolAddress((void**)&pWqr, g_Wqr);
    cudaGetSymbolAddress((void**)&pWB,  g_WB);
    cudaGetSymbolAddress((void**)&pqr,  g_qr);
    cudaGetSymbolAddress((void**)&pP,   g_P);
    cudaGetSymbolAddress((void**)&pQGp, g_QGp);
    float* pPaqi = pP + (size_t)2 * BNN * K2;   // 3 slices of M x 768

    cudaFuncSetAttribute(k_mma_sk, cudaFuncAttributeMaxDynamicSharedMemorySize, SMEM_MMA_BYTES);

    dim3 gRgcn(FF / NT, BNN / MT, 3);            // 6 x 16 x 3 = 288
    dim3 gGate(K2 / NT, BNN / MT, 2);            // 12 x 16 x 2 = 384
    dim3 gAqi (FF / NT, BNN / MT, 3);            // 6 x 16 x 3 = 288
    dim3 gQg  (FF / NT, (BB * LLQ) / MT, 3);     // 6 x 4 x 3 = 72
    dim3 gTr  (K4 / 32, FF / 32, 2);
    dim3 bTr  (32, 8);
    dim3 gQi  (8, 8, 8);
    int cb = (BNN * 192 + 255) / 256;

    // 1: prep(+zero bins); 2: hist; 3: scan; 4: qg GEMM (ncu slot)
    k_prep<<<(N_PREP + 255) / 256, 256>>>((const float4*)Wg, (const float4*)Wq,
                                          (const float4*)q, (const float4*)x);
    k_hist<<<EE / 256, 256>>>(ei, et);
    k_scan<<<1, 1024>>>();
    k_mma_sk<<<gQg, 128, SMEM_MMA_BYTES>>>(pqr, FF, pWgr + FF, 2 * FF, pQGp, FF, FF / 3);
    k_fill<<<EE / 256, 256>>>(ei, et);
    k_transpose_w2<<<gTr, bTr>>>(Wrt1, Wrel1, Wrt2, Wrel2);

    // ---- layer 1: RGCN ----
    k_aggregate<<<NBINS, 192>>>();
    k_mma_sk<<<gRgcn, 128, SMEM_MMA_BYTES>>>(pX4, K4, pWT0, K4, pP, FF, K4 / 3);
    k_combine_relu<<<cb, 256>>>(pP, pH, b1);

    // ---- gate 1: merged [hg|alpha_h] GEMM -> qi -> alpha_qi GEMM -> combine ----
    k_mma_sk<<<gGate, 128, SMEM_MMA_BYTES>>>(pH, K2, pWB, FF, pP, K2, FF / 2);
    k_qi<<<gQi, 96>>>(q, bg);
    k_mma_sk<<<gAqi, 128, SMEM_MMA_BYTES>>>(pH + FF, K2, pWqr + FF, 2 * FF, pPaqi, FF, FF / 3);
    k_gcombine<1><<<cb, 256>>>(pP, pPaqi, pX4, K4, bq, pH);

    // ---- layer 2: RGCN ----
    k_aggregate<<<NBINS, 192>>>();
    k_mma_sk<<<gRgcn, 128, SMEM_MMA_BYTES>>>(pX4, K4, pWT1, K4, pP, FF, K4 / 3);
    k_combine_relu<<<cb, 256>>>(pP, pH, b2);

    // ---- gate 2 ----
    k_mma_sk<<<gGate, 128, SMEM_MMA_BYTES>>>(pH, K2, pWB, FF, pP, K2, FF / 2);
    k_qi<<<gQi, 96>>>(q, bg);
    k_mma_sk<<<gAqi, 128, SMEM_MMA_BYTES>>>(pH + FF, K2, pWqr + FF, 2 * FF, pPaqi, FF, FF / 3);
    k_gcombine<0><<<cb, 256>>>(pP, pPaqi, out, FF, bq, pH);
}

// round 16
// speedup vs baseline: 1.0479x; 1.0479x over previous
#include <cuda_runtime.h>
#include <cstdint>
#include <math.h>

// Problem constants
#define BNN   2048
#define FF    768
#define EE    65536
#define BB    8
#define LLQ   64
#define NREL  3
#define NBINS (BNN*NREL)
#define K4    3072
#define K2    1536
#define ZSPL  3
#define ZQG   12

// ------------------------- device scratch -------------------------
__device__ int   g_bin_cnt[NBINS];
__device__ int   g_bin_off[NBINS];
__device__ int   g_cursor[NBINS];
__device__ float g_inv_cnt[NBINS];
__device__ int   g_sorted_src[EE];
__device__ float g_X4[(size_t)BNN * K4];
__device__ float g_WcatT[2][(size_t)FF * K4];
__device__ float g_H[(size_t)BNN * K2];
__device__ float g_Wgr[(size_t)FF * 2 * FF];
__device__ float g_Wqr[(size_t)FF * 2 * FF];
__device__ float g_qr[(size_t)BB * LLQ * FF];
__device__ float g_P[(size_t)ZSPL * BNN * FF];        // split-K partials
__device__ float g_QGp[(size_t)ZQG * BB * LLQ * FF];  // qg partials (12 slices)
__device__ float g_QG[(size_t)BB * LLQ * FF];         // combined qg (+bg)

__device__ __forceinline__ float sigmoidf_(float x) {
    return __fdividef(1.0f, 1.0f + __expf(-x));
}
__device__ __forceinline__ float tanh_fast(float x) {
    float e = __expf(2.0f * x);
    return 1.0f - __fdividef(2.0f, e + 1.0f);
}
__device__ __forceinline__ float to_tf32(float x) {
    uint32_t u;
    asm("cvt.rna.tf32.f32 %0, %1;" : "=r"(u) : "f"(x));
    return __uint_as_float(u);
}
__device__ __forceinline__ float4 r4(float4 v) {
    return make_float4(to_tf32(v.x), to_tf32(v.y), to_tf32(v.z), to_tf32(v.w));
}
__device__ __forceinline__ float rcp_fast(float x) {
    float r;
    asm("rcp.approx.ftz.f32 %0, %1;" : "=f"(r) : "f"(x));
    return r;
}
__device__ __forceinline__ uint32_t smem_u32(const void* p) {
    uint32_t a;
    asm("{ .reg .u64 t; cvta.to.shared.u64 t, %1; cvt.u32.u64 %0, t; }" : "=r"(a) : "l"(p));
    return a;
}
__device__ __forceinline__ void cp16(uint32_t dst, const void* src) {
    asm volatile("cp.async.cg.shared.global [%0], [%1], 16;" :: "r"(dst), "l"(src));
}
#define CP_COMMIT() asm volatile("cp.async.commit_group;" ::: "memory")
#define CP_WAIT1()  asm volatile("cp.async.wait_group 1;" ::: "memory")
#define CP_WAIT0()  asm volatile("cp.async.wait_group 0;" ::: "memory")

#define MMA_TF32(D, Aa, b0v, b1v) \
    asm volatile("mma.sync.aligned.m16n8k8.row.col.f32.tf32.tf32.f32 " \
        "{%0,%1,%2,%3}, {%4,%5,%6,%7}, {%8,%9}, {%0,%1,%2,%3};" \
        : "+f"((D)[0]), "+f"((D)[1]), "+f"((D)[2]), "+f"((D)[3]) \
        : "r"((Aa)[0]), "r"((Aa)[1]), "r"((Aa)[2]), "r"((Aa)[3]), \
          "r"(b0v), "r"(b1v))

__device__ __forceinline__ void ldsm4(uint32_t addr, uint32_t* r) {
    asm volatile("ldmatrix.sync.aligned.m8n8.x4.shared.b16 {%0,%1,%2,%3}, [%4];"
        : "=r"(r[0]), "=r"(r[1]), "=r"(r[2]), "=r"(r[3]) : "r"(addr));
}

// ------------------------- CSR build -------------------------
__global__ void k_hist(const int* __restrict__ ei, const int* __restrict__ et) {
    int i = blockIdx.x * blockDim.x + threadIdx.x;
    if (i < EE) {
        int dst = ei[EE + i];
        atomicAdd(&g_bin_cnt[dst * NREL + et[i]], 1);
    }
}

__global__ void k_scan() {
    __shared__ int wsum[32];
    int t = threadIdx.x;
    int c[6], loc[6];
    int s = 0;
#pragma unroll
    for (int j = 0; j < 6; ++j) { c[j] = g_bin_cnt[t * 6 + j]; loc[j] = s; s += c[j]; }
    int lane = t & 31, w = t >> 5;
    int v = s;
#pragma unroll
    for (int d = 1; d < 32; d <<= 1) { int u = __shfl_up_sync(0xffffffffu, v, d); if (lane >= d) v += u; }
    if (lane == 31) wsum[w] = v;
    __syncthreads();
    if (w == 0) {
        int u = wsum[lane];
#pragma unroll
        for (int d = 1; d < 32; d <<= 1) { int z = __shfl_up_sync(0xffffffffu, u, d); if (lane >= d) u += z; }
        wsum[lane] = u;
    }
    __syncthreads();
    int base = (w > 0 ? wsum[w - 1] : 0) + (v - s);
#pragma unroll
    for (int j = 0; j < 6; ++j) {
        int idx = t * 6 + j;
        int off = base + loc[j];
        g_bin_off[idx] = off;
        g_cursor[idx]  = off;
        g_inv_cnt[idx] = 1.0f / (float)(c[j] > 0 ? c[j] : 1);
    }
}

__global__ void k_fill(const int* __restrict__ ei, const int* __restrict__ et) {
    int i = blockIdx.x * blockDim.x + threadIdx.x;
    if (i < EE) {
        int dst = ei[EE + i];
        int pos = atomicAdd(&g_cursor[dst * NREL + et[i]], 1);
        g_sorted_src[pos] = ei[i];
    }
}

// ------------------------- fused prep -------------------------
#define N_WG4 (FF * 2 * FF / 4)
#define N_Q4  (BB * LLQ * FF / 4)
#define N_X4  (BNN * FF / 4)
#define N_PREP (2 * N_WG4 + N_Q4 + N_X4)

__global__ void k_prep(const float4* __restrict__ Wg, const float4* __restrict__ Wq,
                       const float4* __restrict__ q, const float4* __restrict__ x) {
    int i = blockIdx.x * blockDim.x + threadIdx.x;
    if (i < NBINS) g_bin_cnt[i] = 0;
    if (i >= N_PREP) return;
    if (i < N_WG4) {
        reinterpret_cast<float4*>(g_Wgr)[i] = r4(Wg[i]);
    } else if (i < 2 * N_WG4) {
        int j = i - N_WG4;
        reinterpret_cast<float4*>(g_Wqr)[j] = r4(Wq[j]);
    } else if (i < 2 * N_WG4 + N_Q4) {
        int j = i - 2 * N_WG4;
        reinterpret_cast<float4*>(g_qr)[j] = r4(q[j]);
    } else {
        int j = i - 2 * N_WG4 - N_Q4;
        int row = j / 192, c = j - row * 192;
        reinterpret_cast<float4*>(g_X4)[(size_t)row * 768 + c] = r4(x[j]);
    }
}

// Dual-layer transpose
__global__ void __launch_bounds__(256) k_transpose_w2(
    const float* __restrict__ Wroot1, const float* __restrict__ Wrel1,
    const float* __restrict__ Wroot2, const float* __restrict__ Wrel2) {
    __shared__ float t[32][33];
    int kb = blockIdx.x * 32, nb = blockIdx.y * 32;
    int layer = blockIdx.z;
    const float* Wroot = layer ? Wroot2 : Wroot1;
    const float* Wrel  = layer ? Wrel2  : Wrel1;
    int tx = threadIdx.x, ty = threadIdx.y;
#pragma unroll
    for (int j = 0; j < 4; ++j) {
        int k = kb + ty + j * 8;
        float v = (k < FF) ? Wroot[(size_t)k * FF + nb + tx]
                           : Wrel[(size_t)(k - FF) * FF + nb + tx];
        t[ty + j * 8][tx] = to_tf32(v);
    }
    __syncthreads();
#pragma unroll
    for (int j = 0; j < 4; ++j) {
        int n = nb + ty + j * 8;
        g_WcatT[layer][(size_t)n * K4 + kb + tx] = t[tx][ty + j * 8];
    }
}

// ------------------------- aggregation -------------------------
__global__ void __launch_bounds__(192) k_aggregate() {
    int bin = blockIdx.x;
    int dst = bin / NREL;
    int rel = bin - dst * NREL;
    int beg = g_bin_off[bin];
    int cnt = g_bin_cnt[bin];
    int t = threadIdx.x;
    const float4* x4 = reinterpret_cast<const float4*>(g_X4);
    float4 acc = make_float4(0.f, 0.f, 0.f, 0.f);
    int sNext = (cnt > 0) ? g_sorted_src[beg] : 0;
    for (int j = 0; j < cnt; ++j) {
        int s = sNext;
        if (j + 1 < cnt) sNext = g_sorted_src[beg + j + 1];
        float4 v = x4[(size_t)s * 768 + t];
        acc.x += v.x; acc.y += v.y; acc.z += v.z; acc.w += v.w;
    }
    float ic = g_inv_cnt[bin];
    acc.x *= ic; acc.y *= ic; acc.z *= ic; acc.w *= ic;
    reinterpret_cast<float4*>(g_X4)[(size_t)dst * 768 + (size_t)(rel + 1) * 192 + t] = r4(acc);
}

// ------------------------- split-K tf32 mma.sync GEMM (R12 core) -----------------
// P[z][M][768] partial = A[M, kOff:kOff+Kh] @ B[:, kOff:kOff+Kh]^T
// CTA tile 128x128, 128 threads = 4 warps (2m x 2n) of 64x64 warp tiles.
#define MT 128
#define NT 128
#define STAGE_FLOATS ((MT + NT) * 32)
#define STAGE_BYTES  (STAGE_FLOATS * 4)
#define SMEM_MMA_BYTES (3 * STAGE_BYTES)

__global__ void __launch_bounds__(128, 2) k_mma_sk(
    const float* __restrict__ A, int lda,
    const float* __restrict__ B, int ldb,
    float* __restrict__ P, int Kh)
{
    extern __shared__ float sm[];
    const int tid = threadIdx.x;
    const int m0 = blockIdx.y * MT;
    const int n0 = blockIdx.x * NT;
    const int Mtot = gridDim.y * MT;
    const int kOff = blockIdx.z * Kh;
    const int wid = tid >> 5, lane = tid & 31;
    const int wm = (wid >> 1) * 64;
    const int wn = (wid & 1) * 64;
    const int g = lane >> 2, t = lane & 3;

    const uint32_t smb = smem_u32(sm);

    const int crow = tid >> 3;
    const int cc = tid & 7;
    const uint32_t physc = (uint32_t)(cc ^ (crow & 7)) * 16u;

    const int l7 = lane & 7, l8 = (lane >> 3) & 1, l16 = (lane >> 4) & 1;
    uint32_t aRow[4];
#pragma unroll
    for (int mt = 0; mt < 4; ++mt)
        aRow[mt] = (uint32_t)(wm + mt * 16 + l7 + l8 * 8) * 128u;
    uint32_t bRow[4];
#pragma unroll
    for (int p = 0; p < 4; ++p)
        bRow[p] = (uint32_t)(MT * 32 * 4) + (uint32_t)(wn + p * 16 + l7 + l16 * 8) * 128u;

    float d[4][8][4];
#pragma unroll
    for (int mt = 0; mt < 4; ++mt)
#pragma unroll
        for (int nt = 0; nt < 8; ++nt)
#pragma unroll
            for (int j = 0; j < 4; ++j) d[mt][nt][j] = 0.f;

    const int nk = Kh >> 5;
    const float* Abase = A + (size_t)(m0 + crow) * lda + kOff + cc * 4;
    const float* Bbase = B + (size_t)(n0 + crow) * ldb + kOff + cc * 4;

    auto issue = [&](int c, int s) {
        uint32_t st = smb + (uint32_t)s * STAGE_BYTES;
        int k0 = c << 5;
#pragma unroll
        for (int i = 0; i < 8; ++i)
            cp16(st + (uint32_t)(crow + 16 * i) * 128u + physc,
                 Abase + (size_t)(16 * i) * lda + k0);
#pragma unroll
        for (int i = 0; i < 8; ++i)
            cp16(st + (uint32_t)(MT * 32 * 4) + (uint32_t)(crow + 16 * i) * 128u + physc,
                 Bbase + (size_t)(16 * i) * ldb + k0);
        CP_COMMIT();
    };

    issue(0, 0);
    if (nk > 1) issue(1, 1);

    int sIss = 2, sCur = 0;
    for (int c = 0; c < nk; ++c) {
        if (c + 1 < nk) CP_WAIT1(); else CP_WAIT0();
        __syncthreads();
        if (c + 2 < nk) { issue(c + 2, sIss); sIss = (sIss == 2) ? 0 : sIss + 1; }

        uint32_t st = smb + (uint32_t)sCur * STAGE_BYTES;
        sCur = (sCur == 2) ? 0 : sCur + 1;

#pragma unroll
        for (int ks = 0; ks < 4; ++ks) {
            uint32_t kaOff = (uint32_t)(((ks * 2 + l16) ^ l7) * 16);
            uint32_t kbOff = (uint32_t)(((ks * 2 + l8) ^ l7) * 16);
            uint32_t aF[4][4], bF[4][4];
#pragma unroll
            for (int mt = 0; mt < 4; ++mt) ldsm4(st + aRow[mt] + kaOff, aF[mt]);
#pragma unroll
            for (int p = 0; p < 4; ++p)    ldsm4(st + bRow[p] + kbOff, bF[p]);
#pragma unroll
            for (int mt = 0; mt < 4; ++mt)
#pragma unroll
                for (int p = 0; p < 4; ++p) {
                    MMA_TF32(d[mt][2 * p],     aF[mt], bF[p][0], bF[p][1]);
                    MMA_TF32(d[mt][2 * p + 1], aF[mt], bF[p][2], bF[p][3]);
                }
        }
    }

    float* Cp = P + (size_t)blockIdx.z * Mtot * FF;
#pragma unroll
    for (int mt = 0; mt < 4; ++mt)
#pragma unroll
        for (int nt = 0; nt < 8; ++nt) {
            int ccc = n0 + wn + nt * 8 + t * 2;
#pragma unroll
            for (int h = 0; h < 2; ++h) {
                int r = m0 + wm + mt * 16 + g + h * 8;
                float2 v = make_float2(d[mt][nt][h * 2 + 0], d[mt][nt][h * 2 + 1]);
                *reinterpret_cast<float2*>(Cp + (size_t)r * FF + ccc) = v;
            }
        }
}

// ------------------------- qg combine: 12 slices + bg -> g_QG ---------------------
__global__ void k_qgcombine(const float* __restrict__ bg) {
    int i = blockIdx.x * blockDim.x + threadIdx.x;   // over 512*192
    if (i >= BB * LLQ * 192) return;
    int c4 = i % 192;
    const float4* P4 = reinterpret_cast<const float4*>(g_QGp);
    float4 v = P4[i];
#pragma unroll
    for (int z = 1; z < ZQG; ++z) {
        float4 b = P4[(size_t)z * (BB * LLQ * 192) + i];
        v.x += b.x; v.y += b.y; v.z += b.z; v.w += b.w;
    }
    float4 b4 = reinterpret_cast<const float4*>(bg)[c4];
    v.x += b4.x; v.y += b4.y; v.z += b4.z; v.w += b4.w;
    reinterpret_cast<float4*>(g_QG)[i] = v;
}

// ------------------------- split-K combine (NZ slices) + fused epilogue -----------
// EPI: 2 relu(+bias)+round, 3 gate+round, 4 gate(no round)
template<int EPI, int NZ>
__global__ void k_combine(const float* __restrict__ P, float* __restrict__ C, int ldc,
                          int Mtot, const float* __restrict__ bias,
                          const float* __restrict__ Hbuf) {
    int i = blockIdx.x * blockDim.x + threadIdx.x;
    if (i >= Mtot * 192) return;
    int row = i / 192, c4 = i - row * 192;
    int col = c4 * 4;
    const float4* P4 = reinterpret_cast<const float4*>(P);
    float4 v = P4[(size_t)row * 192 + c4];
#pragma unroll
    for (int z = 1; z < NZ; ++z) {
        float4 b = P4[(size_t)(z * Mtot + row) * 192 + c4];
        v.x += b.x; v.y += b.y; v.z += b.z; v.w += b.w;
    }
    float4 b4 = reinterpret_cast<const float4*>(bias)[c4];
    v.x += b4.x; v.y += b4.y; v.z += b4.z; v.w += b4.w;
    if (EPI == 2) {
        v.x = to_tf32(fmaxf(v.x, 0.f)); v.y = to_tf32(fmaxf(v.y, 0.f));
        v.z = to_tf32(fmaxf(v.z, 0.f)); v.w = to_tf32(fmaxf(v.w, 0.f));
    } else {
        const float* hp = Hbuf + (size_t)row * K2 + col;
        float4 h4  = *reinterpret_cast<const float4*>(hp);
        float4 qi4 = *reinterpret_cast<const float4*>(hp + FF);
        float al;
        al = sigmoidf_(v.x); v.x = al * tanh_fast(qi4.x) + (1.f - al) * h4.x;
        al = sigmoidf_(v.y); v.y = al * tanh_fast(qi4.y) + (1.f - al) * h4.y;
        al = sigmoidf_(v.z); v.z = al * tanh_fast(qi4.z) + (1.f - al) * h4.z;
        al = sigmoidf_(v.w); v.w = al * tanh_fast(qi4.w) + (1.f - al) * h4.w;
        if (EPI == 3) v = r4(v);
    }
    *reinterpret_cast<float4*>(C + (size_t)row * ldc + col) = v;
}

// ------------------------- fused qi: 4 nodes per rcp, single qg buffer ------------
// qi[b,n,f] = sum_l q / (1 + e^{-hg} e^{-qg}); e^{-x} capped at 1e4 (lossless at fp32
// sigmoid precision, prevents overflow of the 4-way denominator product <= 1e32).
__global__ void __launch_bounds__(96) k_qi(const float* __restrict__ q) {
    int fb = blockIdx.x;
    int nq = blockIdx.y;
    int b  = blockIdx.z;
    int t  = threadIdx.x;
    int f  = fb * 96 + t;

    __shared__ float qs[LLQ * 96];
    float eq[LLQ];
#pragma unroll
    for (int l = 0; l < LLQ; ++l) {
        size_t qidx = ((size_t)(b * LLQ + l)) * FF + f;
        eq[l] = fminf(__expf(-g_QG[qidx]), 1e4f);
        qs[l * 96 + t] = q[qidx];
    }
    __syncthreads();

    int n0 = nq * 32;
    for (int n = n0; n < n0 + 32; n += 4) {
        int node = b * 256 + n;
        size_t hidx = (size_t)node * FF + f;
        float hg[4] = {0.f, 0.f, 0.f, 0.f};
#pragma unroll
        for (int z = 0; z < ZSPL; ++z) {
            const float* Pz = g_P + (size_t)z * BNN * FF;
#pragma unroll
            for (int k = 0; k < 4; ++k) hg[k] += Pz[hidx + (size_t)k * FF];
        }
        float eh0 = fminf(__expf(-hg[0]), 1e4f);
        float eh1 = fminf(__expf(-hg[1]), 1e4f);
        float eh2 = fminf(__expf(-hg[2]), 1e4f);
        float eh3 = fminf(__expf(-hg[3]), 1e4f);
        float a0 = 0.f, a1 = 0.f, a2 = 0.f, a3 = 0.f;
#pragma unroll
        for (int l = 0; l < LLQ; ++l) {
            float qv = qs[l * 96 + t];
            float e = eq[l];
            float d0 = fmaf(eh0, e, 1.0f);
            float d1 = fmaf(eh1, e, 1.0f);
            float d2 = fmaf(eh2, e, 1.0f);
            float d3 = fmaf(eh3, e, 1.0f);
            float d01 = d0 * d1, d23 = d2 * d3;
            float r = rcp_fast(d01 * d23);
            float r01 = r * d23, r23 = r * d01;
            a0 = fmaf(r01 * d1, qv, a0);
            a1 = fmaf(r01 * d0, qv, a1);
            a2 = fmaf(r23 * d3, qv, a2);
            a3 = fmaf(r23 * d2, qv, a3);
        }
        g_H[(size_t)(node + 0) * K2 + FF + f] = to_tf32(a0);
        g_H[(size_t)(node + 1) * K2 + FF + f] = to_tf32(a1);
        g_H[(size_t)(node + 2) * K2 + FF + f] = to_tf32(a2);
        g_H[(size_t)(node + 3) * K2 + FF + f] = to_tf32(a3);
    }
}

// ------------------------- host -------------------------
extern "C" void kernel_launch(void* const* d_in, const int* in_sizes, int n_in,
                              void* d_out, int out_size) {
    const float* x     = (const float*)d_in[0];
    const int*   ei    = (const int*)  d_in[1];
    const int*   et    = (const int*)  d_in[2];
    const float* q     = (const float*)d_in[3];
    const float* Wrel1 = (const float*)d_in[4];
    const float* Wrt1  = (const float*)d_in[5];
    const float* b1    = (const float*)d_in[6];
    const float* Wrel2 = (const float*)d_in[7];
    const float* Wrt2  = (const float*)d_in[8];
    const float* b2    = (const float*)d_in[9];
    const float* Wg    = (const float*)d_in[10];
    const float* bg    = (const float*)d_in[11];
    const float* Wq    = (const float*)d_in[12];
    const float* bq    = (const float*)d_in[13];
    float* out = (float*)d_out;

    float *pX4, *pWT0, *pWT1, *pH, *pWgr, *pWqr, *pqr, *pP, *pQGp;
    cudaGetSymbolAddress((void**)&pX4,  g_X4);
    cudaGetSymbolAddress((void**)&pWT0, g_WcatT);
    pWT1 = pWT0 + (size_t)FF * K4;
    cudaGetSymbolAddress((void**)&pH,   g_H);
    cudaGetSymbolAddress((void**)&pWgr, g_Wgr);
    cudaGetSymbolAddress((void**)&pWqr, g_Wqr);
    cudaGetSymbolAddress((void**)&pqr,  g_qr);
    cudaGetSymbolAddress((void**)&pP,   g_P);
    cudaGetSymbolAddress((void**)&pQGp, g_QGp);

    cudaFuncSetAttribute(k_mma_sk, cudaFuncAttributeMaxDynamicSharedMemorySize, SMEM_MMA_BYTES);

    dim3 gBig(FF / NT, BNN / MT, ZSPL);              // 6 x 16 x 3 = 288
    dim3 gQg (FF / NT, (BB * LLQ) / MT, ZQG);        // 6 x 4 x 12 = 288
    dim3 gTr (K4 / 32, FF / 32, 2);
    dim3 bTr (32, 8);
    dim3 gQi (8, 8, 8);
    int cbBig = (BNN * 192 + 255) / 256;
    int cbQg  = (BB * LLQ * 192 + 255) / 256;

    // 1: prep(+zero bins); 2: hist; 3: scan; 4: qg GEMM @ Z=12 (ncu slot)
    k_prep<<<(N_PREP + 255) / 256, 256>>>((const float4*)Wg, (const float4*)Wq,
                                          (const float4*)q, (const float4*)x);
    k_hist<<<EE / 256, 256>>>(ei, et);
    k_scan<<<1, 1024>>>();
    k_mma_sk<<<gQg, 128, SMEM_MMA_BYTES>>>(pqr, FF, pWgr + FF, 2 * FF, pQGp, FF / ZQG);
    k_qgcombine<<<cbQg, 256>>>(bg);
    k_fill<<<EE / 256, 256>>>(ei, et);
    k_transpose_w2<<<gTr, bTr>>>(Wrt1, Wrel1, Wrt2, Wrel2);

    // ---- layer 1: RGCN ----
    k_aggregate<<<NBINS, 192>>>();
    k_mma_sk<<<gBig, 128, SMEM_MMA_BYTES>>>(pX4, K4, pWT0, K4, pP, K4 / ZSPL);
    k_combine<2, 3><<<cbBig, 256>>>(pP, pH, K2, BNN, b1, nullptr);

    // ---- gate 1 ----
    k_mma_sk<<<gBig, 128, SMEM_MMA_BYTES>>>(pH, K2, pWgr, 2 * FF, pP, FF / ZSPL);  // hg
    k_qi<<<gQi, 96>>>(q);
    k_mma_sk<<<gBig, 128, SMEM_MMA_BYTES>>>(pH, K2, pWqr, 2 * FF, pP, K2 / ZSPL);  // alpha
    k_combine<3, 3><<<cbBig, 256>>>(pP, pX4, K4, BNN, bq, pH);

    // ---- layer 2: RGCN ----
    k_aggregate<<<NBINS, 192>>>();
    k_mma_sk<<<gBig, 128, SMEM_MMA_BYTES>>>(pX4, K4, pWT1, K4, pP, K4 / ZSPL);
    k_combine<2, 3><<<cbBig, 256>>>(pP, pH, K2, BNN, b2, nullptr);

    // ---- gate 2 ----
    k_mma_sk<<<gBig, 128, SMEM_MMA_BYTES>>>(pH, K2, pWgr, 2 * FF, pP, FF / ZSPL);  // hg
    k_qi<<<gQi, 96>>>(q);
    k_mma_sk<<<gBig, 128, SMEM_MMA_BYTES>>>(pH, K2, pWqr, 2 * FF, pP, K2 / ZSPL);  // alpha
    k_combine<4, 3><<<cbBig, 256>>>(pP, out, FF, BNN, bq, pH);
}

// round 17
// speedup vs baseline: 1.0566x; 1.0083x over previous
#include <cuda_runtime.h>
#include <cstdint>
#include <math.h>

// Problem constants
#define BNN   2048
#define FF    768
#define EE    65536
#define BB    8
#define LLQ   64
#define NREL  3
#define NBINS (BNN*NREL)
#define K4    3072
#define K2    1536
#define ZSPL  3
#define ZQG   6

// ------------------------- device scratch -------------------------
__device__ int   g_bin_cnt[NBINS];
__device__ int   g_bin_off[NBINS];
__device__ int   g_cursor[NBINS];
__device__ float g_inv_cnt[NBINS];
__device__ int   g_sorted_src[EE];
__device__ float g_X4[(size_t)BNN * K4];
__device__ float g_WcatT[2][(size_t)FF * K4];
__device__ float g_H[(size_t)BNN * K2];
__device__ float g_Wgr[(size_t)FF * 2 * FF];
__device__ float g_Wqr[(size_t)FF * 2 * FF];
__device__ float g_qr[(size_t)BB * LLQ * FF];
__device__ float g_P[(size_t)ZSPL * BNN * FF];        // split-K partials
__device__ float g_QGp[(size_t)ZQG * BB * LLQ * FF];  // qg partials
__device__ float g_QG[(size_t)BB * LLQ * FF];         // combined qg (+bg)

__device__ __forceinline__ float sigmoidf_(float x) {
    return __fdividef(1.0f, 1.0f + __expf(-x));
}
__device__ __forceinline__ float tanh_fast(float x) {
    float e = __expf(2.0f * x);
    return 1.0f - __fdividef(2.0f, e + 1.0f);
}
__device__ __forceinline__ float to_tf32(float x) {
    uint32_t u;
    asm("cvt.rna.tf32.f32 %0, %1;" : "=r"(u) : "f"(x));
    return __uint_as_float(u);
}
__device__ __forceinline__ float4 r4(float4 v) {
    return make_float4(to_tf32(v.x), to_tf32(v.y), to_tf32(v.z), to_tf32(v.w));
}
__device__ __forceinline__ float rcp_fast(float x) {
    float r;
    asm("rcp.approx.ftz.f32 %0, %1;" : "=f"(r) : "f"(x));
    return r;
}
__device__ __forceinline__ uint32_t smem_u32(const void* p) {
    uint32_t a;
    asm("{ .reg .u64 t; cvta.to.shared.u64 t, %1; cvt.u32.u64 %0, t; }" : "=r"(a) : "l"(p));
    return a;
}
__device__ __forceinline__ void cp16(uint32_t dst, const void* src) {
    asm volatile("cp.async.cg.shared.global [%0], [%1], 16;" :: "r"(dst), "l"(src));
}
#define CP_COMMIT() asm volatile("cp.async.commit_group;" ::: "memory")
#define CP_WAIT1()  asm volatile("cp.async.wait_group 1;" ::: "memory")
#define CP_WAIT0()  asm volatile("cp.async.wait_group 0;" ::: "memory")

#define MMA_TF32(D, Aa, b0v, b1v) \
    asm volatile("mma.sync.aligned.m16n8k8.row.col.f32.tf32.tf32.f32 " \
        "{%0,%1,%2,%3}, {%4,%5,%6,%7}, {%8,%9}, {%0,%1,%2,%3};" \
        : "+f"((D)[0]), "+f"((D)[1]), "+f"((D)[2]), "+f"((D)[3]) \
        : "r"((Aa)[0]), "r"((Aa)[1]), "r"((Aa)[2]), "r"((Aa)[3]), \
          "r"(b0v), "r"(b1v))

__device__ __forceinline__ void ldsm4(uint32_t addr, uint32_t* r) {
    asm volatile("ldmatrix.sync.aligned.m8n8.x4.shared.b16 {%0,%1,%2,%3}, [%4];"
        : "=r"(r[0]), "=r"(r[1]), "=r"(r[2]), "=r"(r[3]) : "r"(addr));
}

// ------------------------- CSR build -------------------------
__global__ void k_hist(const int* __restrict__ ei, const int* __restrict__ et) {
    int i = blockIdx.x * blockDim.x + threadIdx.x;
    if (i < EE) {
        int dst = ei[EE + i];
        atomicAdd(&g_bin_cnt[dst * NREL + et[i]], 1);
    }
}

__global__ void k_scan() {
    __shared__ int wsum[32];
    int t = threadIdx.x;
    int c[6], loc[6];
    int s = 0;
#pragma unroll
    for (int j = 0; j < 6; ++j) { c[j] = g_bin_cnt[t * 6 + j]; loc[j] = s; s += c[j]; }
    int lane = t & 31, w = t >> 5;
    int v = s;
#pragma unroll
    for (int d = 1; d < 32; d <<= 1) { int u = __shfl_up_sync(0xffffffffu, v, d); if (lane >= d) v += u; }
    if (lane == 31) wsum[w] = v;
    __syncthreads();
    if (w == 0) {
        int u = wsum[lane];
#pragma unroll
        for (int d = 1; d < 32; d <<= 1) { int z = __shfl_up_sync(0xffffffffu, u, d); if (lane >= d) u += z; }
        wsum[lane] = u;
    }
    __syncthreads();
    int base = (w > 0 ? wsum[w - 1] : 0) + (v - s);
#pragma unroll
    for (int j = 0; j < 6; ++j) {
        int idx = t * 6 + j;
        int off = base + loc[j];
        g_bin_off[idx] = off;
        g_cursor[idx]  = off;
        g_inv_cnt[idx] = 1.0f / (float)(c[j] > 0 ? c[j] : 1);
    }
}

// Fused: blocks [0, 256) do edge fill; blocks [256, ...) do qg partial combine.
#define FILL_BLKS (EE / 256)                       // 256
#define QGC_N     (BB * LLQ * 192)                 // 98304 float4s
#define QGC_BLKS  ((QGC_N + 255) / 256)            // 384

__global__ void k_fill_qgc(const int* __restrict__ ei, const int* __restrict__ et,
                           const float* __restrict__ bg) {
    if (blockIdx.x < FILL_BLKS) {
        int i = blockIdx.x * 256 + threadIdx.x;
        int dst = ei[EE + i];
        int pos = atomicAdd(&g_cursor[dst * NREL + et[i]], 1);
        g_sorted_src[pos] = ei[i];
    } else {
        int i = (blockIdx.x - FILL_BLKS) * 256 + threadIdx.x;
        if (i >= QGC_N) return;
        int c4 = i % 192;
        const float4* P4 = reinterpret_cast<const float4*>(g_QGp);
        float4 v = P4[i];
#pragma unroll
        for (int z = 1; z < ZQG; ++z) {
            float4 b = P4[(size_t)z * QGC_N + i];
            v.x += b.x; v.y += b.y; v.z += b.z; v.w += b.w;
        }
        float4 b4 = reinterpret_cast<const float4*>(bg)[c4];
        v.x += b4.x; v.y += b4.y; v.z += b4.z; v.w += b4.w;
        reinterpret_cast<float4*>(g_QG)[i] = v;
    }
}

// ------------------------- fused prep -------------------------
#define N_WG4 (FF * 2 * FF / 4)
#define N_Q4  (BB * LLQ * FF / 4)
#define N_X4  (BNN * FF / 4)
#define N_PREP (2 * N_WG4 + N_Q4 + N_X4)

__global__ void k_prep(const float4* __restrict__ Wg, const float4* __restrict__ Wq,
                       const float4* __restrict__ q, const float4* __restrict__ x) {
    int i = blockIdx.x * blockDim.x + threadIdx.x;
    if (i < NBINS) g_bin_cnt[i] = 0;
    if (i >= N_PREP) return;
    if (i < N_WG4) {
        reinterpret_cast<float4*>(g_Wgr)[i] = r4(Wg[i]);
    } else if (i < 2 * N_WG4) {
        int j = i - N_WG4;
        reinterpret_cast<float4*>(g_Wqr)[j] = r4(Wq[j]);
    } else if (i < 2 * N_WG4 + N_Q4) {
        int j = i - 2 * N_WG4;
        reinterpret_cast<float4*>(g_qr)[j] = r4(q[j]);
    } else {
        int j = i - 2 * N_WG4 - N_Q4;
        int row = j / 192, c = j - row * 192;
        reinterpret_cast<float4*>(g_X4)[(size_t)row * 768 + c] = r4(x[j]);
    }
}

// Dual-layer transpose
__global__ void __launch_bounds__(256) k_transpose_w2(
    const float* __restrict__ Wroot1, const float* __restrict__ Wrel1,
    const float* __restrict__ Wroot2, const float* __restrict__ Wrel2) {
    __shared__ float t[32][33];
    int kb = blockIdx.x * 32, nb = blockIdx.y * 32;
    int layer = blockIdx.z;
    const float* Wroot = layer ? Wroot2 : Wroot1;
    const float* Wrel  = layer ? Wrel2  : Wrel1;
    int tx = threadIdx.x, ty = threadIdx.y;
#pragma unroll
    for (int j = 0; j < 4; ++j) {
        int k = kb + ty + j * 8;
        float v = (k < FF) ? Wroot[(size_t)k * FF + nb + tx]
                           : Wrel[(size_t)(k - FF) * FF + nb + tx];
        t[ty + j * 8][tx] = to_tf32(v);
    }
    __syncthreads();
#pragma unroll
    for (int j = 0; j < 4; ++j) {
        int n = nb + ty + j * 8;
        g_WcatT[layer][(size_t)n * K4 + kb + tx] = t[tx][ty + j * 8];
    }
}

// ------------------------- aggregation -------------------------
__global__ void __launch_bounds__(192) k_aggregate() {
    int bin = blockIdx.x;
    int dst = bin / NREL;
    int rel = bin - dst * NREL;
    int beg = g_bin_off[bin];
    int cnt = g_bin_cnt[bin];
    int t = threadIdx.x;
    const float4* x4 = reinterpret_cast<const float4*>(g_X4);
    float4 acc = make_float4(0.f, 0.f, 0.f, 0.f);
    int sNext = (cnt > 0) ? g_sorted_src[beg] : 0;
    for (int j = 0; j < cnt; ++j) {
        int s = sNext;
        if (j + 1 < cnt) sNext = g_sorted_src[beg + j + 1];
        float4 v = x4[(size_t)s * 768 + t];
        acc.x += v.x; acc.y += v.y; acc.z += v.z; acc.w += v.w;
    }
    float ic = g_inv_cnt[bin];
    acc.x *= ic; acc.y *= ic; acc.z *= ic; acc.w *= ic;
    reinterpret_cast<float4*>(g_X4)[(size_t)dst * 768 + (size_t)(rel + 1) * 192 + t] = r4(acc);
}

// ------------------------- split-K tf32 mma.sync GEMM (R12 core) -----------------
#define MT 128
#define NT 128
#define STAGE_FLOATS ((MT + NT) * 32)
#define STAGE_BYTES  (STAGE_FLOATS * 4)
#define SMEM_MMA_BYTES (3 * STAGE_BYTES)

__global__ void __launch_bounds__(128, 2) k_mma_sk(
    const float* __restrict__ A, int lda,
    const float* __restrict__ B, int ldb,
    float* __restrict__ P, int Kh)
{
    extern __shared__ float sm[];
    const int tid = threadIdx.x;
    const int m0 = blockIdx.y * MT;
    const int n0 = blockIdx.x * NT;
    const int Mtot = gridDim.y * MT;
    const int kOff = blockIdx.z * Kh;
    const int wid = tid >> 5, lane = tid & 31;
    const int wm = (wid >> 1) * 64;
    const int wn = (wid & 1) * 64;
    const int g = lane >> 2, t = lane & 3;

    const uint32_t smb = smem_u32(sm);

    const int crow = tid >> 3;
    const int cc = tid & 7;
    const uint32_t physc = (uint32_t)(cc ^ (crow & 7)) * 16u;

    const int l7 = lane & 7, l8 = (lane >> 3) & 1, l16 = (lane >> 4) & 1;
    uint32_t aRow[4];
#pragma unroll
    for (int mt = 0; mt < 4; ++mt)
        aRow[mt] = (uint32_t)(wm + mt * 16 + l7 + l8 * 8) * 128u;
    uint32_t bRow[4];
#pragma unroll
    for (int p = 0; p < 4; ++p)
        bRow[p] = (uint32_t)(MT * 32 * 4) + (uint32_t)(wn + p * 16 + l7 + l16 * 8) * 128u;

    float d[4][8][4];
#pragma unroll
    for (int mt = 0; mt < 4; ++mt)
#pragma unroll
        for (int nt = 0; nt < 8; ++nt)
#pragma unroll
            for (int j = 0; j < 4; ++j) d[mt][nt][j] = 0.f;

    const int nk = Kh >> 5;
    const float* Abase = A + (size_t)(m0 + crow) * lda + kOff + cc * 4;
    const float* Bbase = B + (size_t)(n0 + crow) * ldb + kOff + cc * 4;

    auto issue = [&](int c, int s) {
        uint32_t st = smb + (uint32_t)s * STAGE_BYTES;
        int k0 = c << 5;
#pragma unroll
        for (int i = 0; i < 8; ++i)
            cp16(st + (uint32_t)(crow + 16 * i) * 128u + physc,
                 Abase + (size_t)(16 * i) * lda + k0);
#pragma unroll
        for (int i = 0; i < 8; ++i)
            cp16(st + (uint32_t)(MT * 32 * 4) + (uint32_t)(crow + 16 * i) * 128u + physc,
                 Bbase + (size_t)(16 * i) * ldb + k0);
        CP_COMMIT();
    };

    issue(0, 0);
    if (nk > 1) issue(1, 1);

    int sIss = 2, sCur = 0;
    for (int c = 0; c < nk; ++c) {
        if (c + 1 < nk) CP_WAIT1(); else CP_WAIT0();
        __syncthreads();
        if (c + 2 < nk) { issue(c + 2, sIss); sIss = (sIss == 2) ? 0 : sIss + 1; }

        uint32_t st = smb + (uint32_t)sCur * STAGE_BYTES;
        sCur = (sCur == 2) ? 0 : sCur + 1;

#pragma unroll
        for (int ks = 0; ks < 4; ++ks) {
            uint32_t kaOff = (uint32_t)(((ks * 2 + l16) ^ l7) * 16);
            uint32_t kbOff = (uint32_t)(((ks * 2 + l8) ^ l7) * 16);
            uint32_t aF[4][4], bF[4][4];
#pragma unroll
            for (int mt = 0; mt < 4; ++mt) ldsm4(st + aRow[mt] + kaOff, aF[mt]);
#pragma unroll
            for (int p = 0; p < 4; ++p)    ldsm4(st + bRow[p] + kbOff, bF[p]);
#pragma unroll
            for (int mt = 0; mt < 4; ++mt)
#pragma unroll
                for (int p = 0; p < 4; ++p) {
                    MMA_TF32(d[mt][2 * p],     aF[mt], bF[p][0], bF[p][1]);
                    MMA_TF32(d[mt][2 * p + 1], aF[mt], bF[p][2], bF[p][3]);
                }
        }
    }

    float* Cp = P + (size_t)blockIdx.z * Mtot * FF;
#pragma unroll
    for (int mt = 0; mt < 4; ++mt)
#pragma unroll
        for (int nt = 0; nt < 8; ++nt) {
            int ccc = n0 + wn + nt * 8 + t * 2;
#pragma unroll
            for (int h = 0; h < 2; ++h) {
                int r = m0 + wm + mt * 16 + g + h * 8;
                float2 v = make_float2(d[mt][nt][h * 2 + 0], d[mt][nt][h * 2 + 1]);
                *reinterpret_cast<float2*>(Cp + (size_t)r * FF + ccc) = v;
            }
        }
}

// ------------------------- split-K combine (NZ slices) + fused epilogue -----------
// EPI: 2 relu(+bias)+round, 3 gate+round, 4 gate(no round)
template<int EPI, int NZ>
__global__ void k_combine(const float* __restrict__ P, float* __restrict__ C, int ldc,
                          int Mtot, const float* __restrict__ bias,
                          const float* __restrict__ Hbuf) {
    int i = blockIdx.x * blockDim.x + threadIdx.x;
    if (i >= Mtot * 192) return;
    int row = i / 192, c4 = i - row * 192;
    int col = c4 * 4;
    const float4* P4 = reinterpret_cast<const float4*>(P);
    float4 v = P4[(size_t)row * 192 + c4];
#pragma unroll
    for (int z = 1; z < NZ; ++z) {
        float4 b = P4[(size_t)(z * Mtot + row) * 192 + c4];
        v.x += b.x; v.y += b.y; v.z += b.z; v.w += b.w;
    }
    float4 b4 = reinterpret_cast<const float4*>(bias)[c4];
    v.x += b4.x; v.y += b4.y; v.z += b4.z; v.w += b4.w;
    if (EPI == 2) {
        v.x = to_tf32(fmaxf(v.x, 0.f)); v.y = to_tf32(fmaxf(v.y, 0.f));
        v.z = to_tf32(fmaxf(v.z, 0.f)); v.w = to_tf32(fmaxf(v.w, 0.f));
    } else {
        const float* hp = Hbuf + (size_t)row * K2 + col;
        float4 h4  = *reinterpret_cast<const float4*>(hp);
        float4 qi4 = *reinterpret_cast<const float4*>(hp + FF);
        float al;
        al = sigmoidf_(v.x); v.x = al * tanh_fast(qi4.x) + (1.f - al) * h4.x;
        al = sigmoidf_(v.y); v.y = al * tanh_fast(qi4.y) + (1.f - al) * h4.y;
        al = sigmoidf_(v.z); v.z = al * tanh_fast(qi4.z) + (1.f - al) * h4.z;
        al = sigmoidf_(v.w); v.w = al * tanh_fast(qi4.w) + (1.f - al) * h4.w;
        if (EPI == 3) v = r4(v);
    }
    *reinterpret_cast<float4*>(C + (size_t)row * ldc + col) = v;
}

// ------------------------- fused qi: 4 nodes per rcp ------------------------------
__global__ void __launch_bounds__(96) k_qi(const float* __restrict__ q) {
    int fb = blockIdx.x;
    int nq = blockIdx.y;
    int b  = blockIdx.z;
    int t  = threadIdx.x;
    int f  = fb * 96 + t;

    __shared__ float qs[LLQ * 96];
    float eq[LLQ];
#pragma unroll
    for (int l = 0; l < LLQ; ++l) {
        size_t qidx = ((size_t)(b * LLQ + l)) * FF + f;
        eq[l] = fminf(__expf(-g_QG[qidx]), 1e4f);
        qs[l * 96 + t] = q[qidx];
    }
    __syncthreads();

    int n0 = nq * 32;
    for (int n = n0; n < n0 + 32; n += 4) {
        int node = b * 256 + n;
        size_t hidx = (size_t)node * FF + f;
        float hg[4] = {0.f, 0.f, 0.f, 0.f};
#pragma unroll
        for (int z = 0; z < ZSPL; ++z) {
            const float* Pz = g_P + (size_t)z * BNN * FF;
#pragma unroll
            for (int k = 0; k < 4; ++k) hg[k] += Pz[hidx + (size_t)k * FF];
        }
        float eh0 = fminf(__expf(-hg[0]), 1e4f);
        float eh1 = fminf(__expf(-hg[1]), 1e4f);
        float eh2 = fminf(__expf(-hg[2]), 1e4f);
        float eh3 = fminf(__expf(-hg[3]), 1e4f);
        float a0 = 0.f, a1 = 0.f, a2 = 0.f, a3 = 0.f;
#pragma unroll
        for (int l = 0; l < LLQ; ++l) {
            float qv = qs[l * 96 + t];
            float e = eq[l];
            float d0 = fmaf(eh0, e, 1.0f);
            float d1 = fmaf(eh1, e, 1.0f);
            float d2 = fmaf(eh2, e, 1.0f);
            float d3 = fmaf(eh3, e, 1.0f);
            float d01 = d0 * d1, d23 = d2 * d3;
            float r = rcp_fast(d01 * d23);
            float r01 = r * d23, r23 = r * d01;
            a0 = fmaf(r01 * d1, qv, a0);
            a1 = fmaf(r01 * d0, qv, a1);
            a2 = fmaf(r23 * d3, qv, a2);
            a3 = fmaf(r23 * d2, qv, a3);
        }
        g_H[(size_t)(node + 0) * K2 + FF + f] = to_tf32(a0);
        g_H[(size_t)(node + 1) * K2 + FF + f] = to_tf32(a1);
        g_H[(size_t)(node + 2) * K2 + FF + f] = to_tf32(a2);
        g_H[(size_t)(node + 3) * K2 + FF + f] = to_tf32(a3);
    }
}

// ------------------------- host -------------------------
extern "C" void kernel_launch(void* const* d_in, const int* in_sizes, int n_in,
                              void* d_out, int out_size) {
    const float* x     = (const float*)d_in[0];
    const int*   ei    = (const int*)  d_in[1];
    const int*   et    = (const int*)  d_in[2];
    const float* q     = (const float*)d_in[3];
    const float* Wrel1 = (const float*)d_in[4];
    const float* Wrt1  = (const float*)d_in[5];
    const float* b1    = (const float*)d_in[6];
    const float* Wrel2 = (const float*)d_in[7];
    const float* Wrt2  = (const float*)d_in[8];
    const float* b2    = (const float*)d_in[9];
    const float* Wg    = (const float*)d_in[10];
    const float* bg    = (const float*)d_in[11];
    const float* Wq    = (const float*)d_in[12];
    const float* bq    = (const float*)d_in[13];
    float* out = (float*)d_out;

    float *pX4, *pWT0, *pWT1, *pH, *pWgr, *pWqr, *pqr, *pP, *pQGp;
    cudaGetSymbolAddress((void**)&pX4,  g_X4);
    cudaGetSymbolAddress((void**)&pWT0, g_WcatT);
    pWT1 = pWT0 + (size_t)FF * K4;
    cudaGetSymbolAddress((void**)&pH,   g_H);
    cudaGetSymbolAddress((void**)&pWgr, g_Wgr);
    cudaGetSymbolAddress((void**)&pWqr, g_Wqr);
    cudaGetSymbolAddress((void**)&pqr,  g_qr);
    cudaGetSymbolAddress((void**)&pP,   g_P);
    cudaGetSymbolAddress((void**)&pQGp, g_QGp);

    cudaFuncSetAttribute(k_mma_sk, cudaFuncAttributeMaxDynamicSharedMemorySize, SMEM_MMA_BYTES);

    dim3 gBig(FF / NT, BNN / MT, ZSPL);              // 6 x 16 x 3 = 288
    dim3 gQg (FF / NT, (BB * LLQ) / MT, ZQG);        // 6 x 4 x 6 = 144, nk=4
    dim3 gTr (K4 / 32, FF / 32, 2);
    dim3 bTr (32, 8);
    dim3 gQi (8, 8, 8);
    int cbBig = (BNN * 192 + 255) / 256;

    // 1: prep(+zero bins); 2: hist; 3: scan; 4: qg GEMM @ Z=6 (ncu slot)
    k_prep<<<(N_PREP + 255) / 256, 256>>>((const float4*)Wg, (const float4*)Wq,
                                          (const float4*)q, (const float4*)x);
    k_hist<<<EE / 256, 256>>>(ei, et);
    k_scan<<<1, 1024>>>();
    k_mma_sk<<<gQg, 128, SMEM_MMA_BYTES>>>(pqr, FF, pWgr + FF, 2 * FF, pQGp, FF / ZQG);
    k_fill_qgc<<<FILL_BLKS + QGC_BLKS, 256>>>(ei, et, bg);
    k_transpose_w2<<<gTr, bTr>>>(Wrt1, Wrel1, Wrt2, Wrel2);

    // ---- layer 1: RGCN ----
    k_aggregate<<<NBINS, 192>>>();
    k_mma_sk<<<gBig, 128, SMEM_MMA_BYTES>>>(pX4, K4, pWT0, K4, pP, K4 / ZSPL);
    k_combine<2, 3><<<cbBig, 256>>>(pP, pH, K2, BNN, b1, nullptr);

    // ---- gate 1 ----
    k_mma_sk<<<gBig, 128, SMEM_MMA_BYTES>>>(pH, K2, pWgr, 2 * FF, pP, FF / ZSPL);  // hg
    k_qi<<<gQi, 96>>>(q);
    k_mma_sk<<<gBig, 128, SMEM_MMA_BYTES>>>(pH, K2, pWqr, 2 * FF, pP, K2 / ZSPL);  // alpha
    k_combine<3, 3><<<cbBig, 256>>>(pP, pX4, K4, BNN, bq, pH);

    // ---- layer 2: RGCN ----
    k_aggregate<<<NBINS, 192>>>();
    k_mma_sk<<<gBig, 128, SMEM_MMA_BYTES>>>(pX4, K4, pWT1, K4, pP, K4 / ZSPL);
    k_combine<2, 3><<<cbBig, 256>>>(pP, pH, K2, BNN, b2, nullptr);

    // ---- gate 2 ----
    k_mma_sk<<<gBig, 128, SMEM_MMA_BYTES>>>(pH, K2, pWgr, 2 * FF, pP, FF / ZSPL);  // hg
    k_qi<<<gQi, 96>>>(q);
    k_mma_sk<<<gBig, 128, SMEM_MMA_BYTES>>>(pH, K2, pWqr, 2 * FF, pP, K2 / ZSPL);  // alpha
    k_combine<4, 3><<<cbBig, 256>>>(pP, out, FF, BNN, bq, pH);
}